// round 1
// baseline (speedup 1.0000x reference)
#include <cuda_runtime.h>
#include <cstdint>

#define NN   1000
#define FF   64
#define BB   16
#define TT   12
#define KCHEB 5
#define CC   10
#define EE   16000
#define SS   (BB*TT)          // 192 snapshots
#define MM   (SS*NN)          // 192000 rows
#define KDIM 576              // 9 * 64
#define NOUT 128              // z(64) + h(64)
#define FLAT (TT*NN*FF)       // 768000 per batch

// ------------------------- device scratch (static, allowed) -------------------------
__device__ int   g_deg_out[NN];
__device__ int   g_deg_in[NN];
__device__ int   g_ptr_out[NN + 1];
__device__ int   g_ptr_in[NN + 1];
__device__ int   g_cur_out[NN];
__device__ int   g_cur_in[NN];
__device__ int   g_nbr_out[EE];
__device__ float g_val_out[EE];
__device__ int   g_nbr_in[EE];
__device__ float g_invdeg_in[NN];
__device__ float g_Wc[KDIM * NOUT];           // 576 x 128 combined weights
__device__ float g_basis[(size_t)MM * KDIM];  // 442 MB: [m][9*64] Chebyshev basis
__device__ float g_hln[(size_t)MM * FF];      // 49 MB: post-LN hidden

// ------------------------------- small helpers -------------------------------
__device__ __forceinline__ unsigned long long ffma2(unsigned long long a,
                                                    unsigned long long b,
                                                    unsigned long long c) {
    unsigned long long d;
    asm("fma.rn.f32x2 %0, %1, %2, %3;" : "=l"(d) : "l"(a), "l"(b), "l"(c));
    return d;
}

// ------------------------------- setup kernels -------------------------------
__global__ void k_init() {
    int i = blockIdx.x * blockDim.x + threadIdx.x;
    if (i < NN) { g_deg_out[i] = 0; g_deg_in[i] = 0; }
}

__global__ void k_deg(const int* __restrict__ ei) {
    int e = blockIdx.x * blockDim.x + threadIdx.x;
    if (e < EE) {
        atomicAdd(&g_deg_out[ei[e]], 1);       // row = src
        atomicAdd(&g_deg_in[ei[EE + e]], 1);   // col = dst
    }
}

__global__ void k_scan() {
    __shared__ int buf[1024];
    int t = threadIdx.x;
    // scan deg_in -> ptr_out (CSR grouped by dst)
    int v = (t < NN) ? g_deg_in[t] : 0;
    buf[t] = v; __syncthreads();
    for (int off = 1; off < 1024; off <<= 1) {
        int a = buf[t];
        int b = (t >= off) ? buf[t - off] : 0;
        __syncthreads();
        buf[t] = a + b;
        __syncthreads();
    }
    if (t < NN) {
        int incl = buf[t];
        g_ptr_out[t] = incl - v;
        g_cur_out[t] = incl - v;
        g_invdeg_in[t] = (v > 0) ? 1.0f / (float)v : 0.0f;
        if (t == NN - 1) g_ptr_out[NN] = incl;
    }
    __syncthreads();
    // scan deg_out -> ptr_in (CSR grouped by row/src)
    int v2 = (t < NN) ? g_deg_out[t] : 0;
    buf[t] = v2; __syncthreads();
    for (int off = 1; off < 1024; off <<= 1) {
        int a = buf[t];
        int b = (t >= off) ? buf[t - off] : 0;
        __syncthreads();
        buf[t] = a + b;
        __syncthreads();
    }
    if (t < NN) {
        int incl = buf[t];
        g_ptr_in[t] = incl - v2;
        g_cur_in[t] = incl - v2;
        if (t == NN - 1) g_ptr_in[NN] = incl;
    }
}

__global__ void k_fill(const int* __restrict__ ei) {
    int e = blockIdx.x * blockDim.x + threadIdx.x;
    if (e < EE) {
        int row = ei[e], col = ei[EE + e];
        int p = atomicAdd(&g_cur_out[col], 1);
        g_nbr_out[p] = row;
        g_val_out[p] = 1.0f / (float)g_deg_out[row];
        int q = atomicAdd(&g_cur_in[row], 1);
        g_nbr_in[q] = col;
    }
}

// Build combined weight  Wc[j*64+i][c]:  c<64 -> z gate (W_z),  c>=64 -> h gate (W_h)
// slot j=0 : W[0,0]+W[1,0];  j=1..4 : out-dir W[0,j];  j=5..8 : in-dir W[1,j-4]
// Only in-channels 0..63 (hidden state is zero).
__global__ void k_wc(const float* __restrict__ Wz, const float* __restrict__ Wh) {
    int idx = blockIdx.x * blockDim.x + threadIdx.x;
    if (idx >= 9 * 64 * 128) return;
    int j = idx / 8192;
    int r = idx - j * 8192;
    int i = r >> 7;
    int c = r & 127;
    const float* W = (c < 64) ? Wz : Wh;
    int f = c & 63;
    float val;
    if (j == 0)       val = W[i * 64 + f] + W[5 * 8192 + i * 64 + f];
    else if (j <= 4)  val = W[(size_t)j * 8192 + i * 64 + f];
    else              val = W[(size_t)(5 + (j - 4)) * 8192 + i * 64 + f];
    g_Wc[(j * 64 + i) * 128 + c] = val;
}

// copy x into basis slot 0   (x layout [B,T,N,F] == row-major [m][f])
__global__ void k_copyx(const float4* __restrict__ x4) {
    int idx = blockIdx.x * blockDim.x + threadIdx.x;   // MM*16 float4
    if (idx >= MM * 16) return;
    int m = idx >> 4;
    int q = idx & 15;
    float4* dst = (float4*)g_basis;
    dst[(size_t)m * 144 + q] = x4[(size_t)m * 16 + q];
}

// ------------------------------- propagation -------------------------------
// step k: out-dir:  slot k   = alpha*prop_out(slot k-1) - slot (k-2)
//         in-dir :  slot 4+k = alpha*prop_in (slot 4+k-1) - slot (k-2)   [ref's quirk:
//         the in-direction subtracts the OUT-direction Chebyshev term]
// k=1: src = slot 0 for both, no subtraction, alpha = 1; k>=2: alpha = 2.
__global__ void k_prop(int step) {
    int s    = blockIdx.y;
    int dir  = blockIdx.z;           // 0 = out, 1 = in
    int warp = threadIdx.x >> 5;
    int lane = threadIdx.x & 31;
    int n = blockIdx.x * 8 + warp;   // 125*8 = 1000

    int srcslot = (step == 1) ? 0 : ((dir ? 4 : 0) + step - 1);
    int dstslot = (dir ? 4 : 0) + step;
    float alpha = (step == 1) ? 1.0f : 2.0f;

    const int* ptr = dir ? g_ptr_in : g_ptr_out;
    const int* nbr = dir ? g_nbr_in : g_nbr_out;

    int e0 = ptr[n], e1 = ptr[n + 1];
    const float2* base = (const float2*)(g_basis + (size_t)s * NN * KDIM + srcslot * 64);

    float2 acc = make_float2(0.f, 0.f);
    if (dir) {
        for (int e = e0; e < e1; e++) {
            int v = __ldg(nbr + e);
            float2 h = __ldg(base + (size_t)v * 288 + lane);
            acc.x += h.x; acc.y += h.y;
        }
        float inv = g_invdeg_in[n];
        acc.x *= inv; acc.y *= inv;
    } else {
        for (int e = e0; e < e1; e++) {
            int v = __ldg(nbr + e);
            float w = __ldg(g_val_out + e);
            float2 h = __ldg(base + (size_t)v * 288 + lane);
            acc.x += w * h.x; acc.y += w * h.y;
        }
    }

    size_t orow = (size_t)(s * NN + n) * KDIM;
    float2 res = make_float2(alpha * acc.x, alpha * acc.y);
    if (step >= 2) {
        float2 sub = ((const float2*)(g_basis + orow + (size_t)(step - 2) * 64))[lane];
        res.x -= sub.x; res.y -= sub.y;
    }
    ((float2*)(g_basis + orow + (size_t)dstslot * 64))[lane] = res;
}

// ------------------------------- fused GEMM + gate + LN -------------------------------
// C[192000,128] = basis[192000,576] @ Wc[576,128]; per row: z = C[:,0:64], g = C[:,64:128]
// h = relu((1-sigmoid(z+bz)) * tanh(g+bh));  LayerNorm over 64; write g_hln.
// Thread (tm,tn): rows tm*8..+7, columns f = tn + 16*j (j=0..3) for BOTH z and h halves.
__global__ void __launch_bounds__(256, 2)
k_gemm(const float* __restrict__ bz, const float* __restrict__ bh,
       const float* __restrict__ lng, const float* __restrict__ lnb) {
    __shared__ float As[16][128];     // A tile transposed: As[k][m]
    __shared__ float Bsd[16][256];    // B tile, each value duplicated: {b,b} pairs

    int tid = threadIdx.x;
    int m0  = blockIdx.x * 128;
    int tm  = tid >> 4;     // 0..15  (row group)
    int tn  = tid & 15;     // 0..15  (col group)

    unsigned long long acc[4][8];
#pragma unroll
    for (int q = 0; q < 4; q++)
#pragma unroll
        for (int j = 0; j < 8; j++) acc[q][j] = 0ull;

    for (int kt = 0; kt < KDIM; kt += 16) {
#pragma unroll
        for (int l = 0; l < 2; l++) {           // A tile: 512 float4, 2/thread
            int fi = tid + l * 256;
            int row = fi >> 2, c4 = fi & 3;
            float4 v = *(const float4*)(g_basis + (size_t)(m0 + row) * KDIM + kt + c4 * 4);
            As[c4 * 4 + 0][row] = v.x;
            As[c4 * 4 + 1][row] = v.y;
            As[c4 * 4 + 2][row] = v.z;
            As[c4 * 4 + 3][row] = v.w;
        }
#pragma unroll
        for (int l = 0; l < 2; l++) {           // B tile (dup-packed)
            int fi = tid + l * 256;
            int kk = fi >> 5, c4 = fi & 31;
            float4 v = *(const float4*)(g_Wc + (size_t)(kt + kk) * 128 + c4 * 4);
            float4 a = make_float4(v.x, v.x, v.y, v.y);
            float4 b = make_float4(v.z, v.z, v.w, v.w);
            *(float4*)&Bsd[kk][c4 * 8]     = a;
            *(float4*)&Bsd[kk][c4 * 8 + 4] = b;
        }
        __syncthreads();

        const unsigned long long* A64 = (const unsigned long long*)&As[0][0];
        const unsigned long long* B64 = (const unsigned long long*)&Bsd[0][0];
#pragma unroll
        for (int kk = 0; kk < 16; kk++) {
            unsigned long long ap[4], bp[8];
#pragma unroll
            for (int q = 0; q < 4; q++) ap[q] = A64[kk * 64 + tm * 4 + q];
#pragma unroll
            for (int j = 0; j < 4; j++) {
                bp[j]     = B64[kk * 128 + j * 16 + tn];        // z cols
                bp[j + 4] = B64[kk * 128 + 64 + j * 16 + tn];   // h cols
            }
#pragma unroll
            for (int q = 0; q < 4; q++)
#pragma unroll
                for (int j = 0; j < 8; j++) acc[q][j] = ffma2(ap[q], bp[j], acc[q][j]);
        }
        __syncthreads();
    }

    // ---- epilogue: gates + relu + LayerNorm (register + 16-lane shuffle only) ----
    float bz4[4], bh4[4], g4[4], b4[4];
#pragma unroll
    for (int j = 0; j < 4; j++) {
        int f = tn + 16 * j;
        bz4[j] = bz[f]; bh4[j] = bh[f]; g4[j] = lng[f]; b4[j] = lnb[f];
    }
#pragma unroll
    for (int q = 0; q < 4; q++) {
#pragma unroll
        for (int h = 0; h < 2; h++) {
            int m = m0 + tm * 8 + 2 * q + h;
            float v[4], s1 = 0.f, s2 = 0.f;
#pragma unroll
            for (int j = 0; j < 4; j++) {
                float2 pz = *(float2*)&acc[q][j];
                float2 pg = *(float2*)&acc[q][j + 4];
                float zp = (h ? pz.y : pz.x) + bz4[j];
                float gp = (h ? pg.y : pg.x) + bh4[j];
                float zs = __fdividef(1.0f, 1.0f + __expf(-zp));
                float th = 1.0f - __fdividef(2.0f, __expf(2.0f * gp) + 1.0f);
                float val = (1.0f - zs) * th;
                val = val > 0.f ? val : 0.f;     // relu before LN
                v[j] = val; s1 += val; s2 += val * val;
            }
#pragma unroll
            for (int msk = 1; msk < 16; msk <<= 1) {
                s1 += __shfl_xor_sync(0xffffffffu, s1, msk);
                s2 += __shfl_xor_sync(0xffffffffu, s2, msk);
            }
            float mean = s1 * (1.0f / 64.0f);
            float var  = s2 * (1.0f / 64.0f) - mean * mean;
            float rstd = rsqrtf(var + 1e-5f);
#pragma unroll
            for (int j = 0; j < 4; j++) {
                g_hln[(size_t)m * 64 + tn + 16 * j] = (v[j] - mean) * rstd * g4[j] + b4[j];
            }
        }
    }
}

// ------------------------------- final linear -------------------------------
__global__ void k_outinit(const float* __restrict__ lb, float* __restrict__ out) {
    int t = threadIdx.x;
    if (t < BB * CC) out[t] = lb[t % CC];
}

__global__ void k_final(const float* __restrict__ lw, float* __restrict__ out) {
    __shared__ float ws[10][1024];
    __shared__ float psum[8][16][10];
    int tid = threadIdx.x;
    int i0 = blockIdx.x * 1024;
    for (int idx = tid; idx < 10 * 1024; idx += 256) {
        int c = idx >> 10, ii = idx & 1023;
        ws[c][ii] = lw[(size_t)c * FLAT + i0 + ii];
    }
    __syncthreads();
    int wp = tid >> 5, lane = tid & 31;
    for (int b = 0; b < BB; b++) {
        float a[10];
#pragma unroll
        for (int c = 0; c < 10; c++) a[c] = 0.f;
#pragma unroll
        for (int r = 0; r < 4; r++) {
            int ii = r * 256 + tid;
            float hv = g_hln[(size_t)b * FLAT + i0 + ii];
#pragma unroll
            for (int c = 0; c < 10; c++) a[c] += hv * ws[c][ii];
        }
#pragma unroll
        for (int c = 0; c < 10; c++) {
            float s = a[c];
#pragma unroll
            for (int msk = 16; msk >= 1; msk >>= 1)
                s += __shfl_xor_sync(0xffffffffu, s, msk);
            if (lane == 0) psum[wp][b][c] = s;
        }
    }
    __syncthreads();
    if (tid < 160) {
        int b = tid / 10, c = tid % 10;
        float s = 0.f;
#pragma unroll
        for (int w = 0; w < 8; w++) s += psum[w][b][c];
        atomicAdd(&out[b * 10 + c], s);
    }
}

// ------------------------------- launcher -------------------------------
extern "C" void kernel_launch(void* const* d_in, const int* in_sizes, int n_in,
                              void* d_out, int out_size) {
    const float* x   = (const float*)d_in[0];
    const int*   ei  = (const int*)  d_in[1];
    const float* Wz  = (const float*)d_in[2];
    const float* bz  = (const float*)d_in[3];
    // d_in[4] = W_r, d_in[5] = b_r  -- provably unused (hidden state is zero)
    const float* Wh  = (const float*)d_in[6];
    const float* bh  = (const float*)d_in[7];
    const float* lng = (const float*)d_in[8];
    const float* lnb = (const float*)d_in[9];
    const float* lw  = (const float*)d_in[10];
    const float* lb  = (const float*)d_in[11];
    float* out = (float*)d_out;

    k_init<<<(NN + 255) / 256, 256>>>();
    k_deg<<<(EE + 255) / 256, 256>>>(ei);
    k_scan<<<1, 1024>>>();
    k_fill<<<(EE + 255) / 256, 256>>>(ei);
    k_wc<<<(9 * 64 * 128 + 255) / 256, 256>>>(Wz, Wh);
    k_copyx<<<(MM * 16) / 256, 256>>>((const float4*)x);
    for (int k = 1; k <= 4; k++)
        k_prop<<<dim3(125, SS, 2), 256>>>(k);
    k_gemm<<<MM / 128, 256>>>(bz, bh, lng, lnb);
    k_outinit<<<1, 256>>>(lb, out);
    k_final<<<FLAT / 1024, 256>>>(lw, out);
}